// round 15
// baseline (speedup 1.0000x reference)
#include <cuda_runtime.h>
#include <cuda_bf16.h>
#include <cstdint>
#include <cstring>

#define NB 4
#define CIN 512
#define C8 64
#define NN 4096

// ---------------- scratch (static; no allocs allowed) ----------------
__device__ __align__(16) __nv_bfloat16 g_ft_h[NB * NN * C8];
__device__ __align__(16) __nv_bfloat16 g_ft_l[NB * NN * C8];
__device__ __align__(16) __nv_bfloat16 g_gt_h[NB * NN * C8];
__device__ __align__(16) __nv_bfloat16 g_gt_l[NB * NN * C8];
__device__ __align__(16) __nv_bfloat16 g_h_h[NB * C8 * NN];
__device__ __align__(16) __nv_bfloat16 g_h_l[NB * C8 * NN];
__device__ __align__(16) __nv_bfloat16 g_wv_h[CIN * C8];
__device__ __align__(16) __nv_bfloat16 g_wv_l[CIN * C8];

// ---------------- helpers ----------------
__device__ __forceinline__ uint32_t smem_u32(const void* p) {
    uint32_t a;
    asm("{ .reg .u64 t; cvta.to.shared.u64 t, %1; cvt.u32.u64 %0, t; }" : "=r"(a) : "l"(p));
    return a;
}

__device__ __forceinline__ float fast_exp(float x) {
    float t = fmaxf(x * 1.4426950408889634f, -126.0f);
    float fi = floorf(t);
    float r = t - fi;
    float p =       1.5403530e-4f;
    p = fmaf(p, r,  1.3333558e-3f);
    p = fmaf(p, r,  9.6181291e-3f);
    p = fmaf(p, r,  5.5504109e-2f);
    p = fmaf(p, r,  2.4022651e-1f);
    p = fmaf(p, r,  6.9314718e-1f);
    p = fmaf(p, r,  1.0f);
    return __int_as_float(((int)fi + 127) << 23) * p;
}

// sm_75/80-era ops — legal on EVERY compilation pass.
#define LDSM4(r, a) \
    asm volatile("ldmatrix.sync.aligned.m8n8.x4.shared.b16 {%0,%1,%2,%3},[%4];" \
        : "=r"((r)[0]), "=r"((r)[1]), "=r"((r)[2]), "=r"((r)[3]) : "r"(a))
#define LDSM4T(r, a) \
    asm volatile("ldmatrix.sync.aligned.m8n8.x4.trans.shared.b16 {%0,%1,%2,%3},[%4];" \
        : "=r"((r)[0]), "=r"((r)[1]), "=r"((r)[2]), "=r"((r)[3]) : "r"(a))
#define MOVMAT(d, s) \
    asm volatile("movmatrix.sync.aligned.m8n8.trans.b16 %0, %1;" : "=r"(d) : "r"(s))
#define CP_ASYNC16(dst, src) \
    asm volatile("cp.async.cg.shared.global [%0], [%1], 16;" :: "r"(dst), "l"(src))
#define CP_COMMIT() asm volatile("cp.async.commit_group;" ::: "memory")
#define CP_WAIT0()  asm volatile("cp.async.wait_group 0;" ::: "memory")

__device__ __forceinline__ void mma_bf16(float* d, const uint32_t* a, uint32_t b0, uint32_t b1) {
    asm volatile("mma.sync.aligned.m16n8k16.row.col.f32.bf16.bf16.f32 "
                 "{%0,%1,%2,%3},{%4,%5,%6,%7},{%8,%9},{%0,%1,%2,%3};"
                 : "+f"(d[0]), "+f"(d[1]), "+f"(d[2]), "+f"(d[3])
                 : "r"(a[0]), "r"(a[1]), "r"(a[2]), "r"(a[3]), "r"(b0), "r"(b1));
}

__device__ __forceinline__ uint32_t pack_bf2(float a, float b) {
    __nv_bfloat162 h2 = __floats2bfloat162_rn(a, b);
    uint32_t u; memcpy(&u, &h2, 4); return u;
}

// ---------------------------------------------------------------------------
// Kernel 0: convert Wv fp32 -> split-bf16 (read 128x by attn epilogue).
// ---------------------------------------------------------------------------
__global__ void wvconv_kernel(const float* __restrict__ Wv) {
    int idx = blockIdx.x * 256 + threadIdx.x;     // 512*64 = 32768
    if (idx >= CIN * C8) return;
    float v = Wv[idx];
    __nv_bfloat16 h = __float2bfloat16_rn(v);
    g_wv_h[idx] = h;
    g_wv_l[idx] = __float2bfloat16_rn(v - __bfloat162float(h));
}

// ---------------------------------------------------------------------------
// Kernel 1: QKV — R13 version (proven 52.7us).
// ---------------------------------------------------------------------------
#define XP 272
#define WP 144
#define QK_XH 0
#define QK_XL 17408
#define QK_W  34816
#define SMEM_QKV 90112

__global__ __launch_bounds__(256) void qkv_kernel(const float* __restrict__ x,
                                                  const float* __restrict__ Wf,
                                                  const float* __restrict__ Wg,
                                                  const float* __restrict__ Wh) {
    extern __shared__ char sm[];
    const uint32_t sb = smem_u32(sm);
    const int tid = threadIdx.x, wid = tid >> 5, lane = tid & 31;
    const int g = lane >> 2, tg = lane & 3;
    const int n0 = blockIdx.x * 128;
    const int b  = blockIdx.y;
    const float* xb = x + (size_t)b * CIN * NN;
    const float* Wp[3] = { Wf, Wg, Wh };

    const uint32_t at_row = (lane & 7) + ((lane >> 4) & 1) * 8;
    const uint32_t at_cb  = ((lane >> 3) & 1) * 16;
    const uint32_t aX  = sb + QK_XH + at_row * XP + wid * 32 + at_cb;
    const uint32_t aXl = aX + (QK_XL - QK_XH);
    const uint32_t b_row = ((lane >> 4) & 1) * 8 + (lane & 7);
    const uint32_t b_cb  = ((lane >> 3) & 1) * 16;
    const uint32_t aW0 = sb + QK_W + b_row * WP + b_cb;

    float d[3][8][4] = {};

    for (int kci = 0; kci < 8; ++kci) {
        const int kc = kci * 64;
        __syncthreads();
        #pragma unroll
        for (int r = 0; r < 8; ++r) {
            int idx = r * 256 + tid;
            int c = idx >> 5, f4 = idx & 31;
            int n = f4 * 4;
            float4 xv = *(const float4*)&xb[(size_t)(kc + c) * NN + n0 + n];
            __nv_bfloat16 h0 = __float2bfloat16_rn(xv.x);
            __nv_bfloat16 h1 = __float2bfloat16_rn(xv.y);
            __nv_bfloat16 h2 = __float2bfloat16_rn(xv.z);
            __nv_bfloat16 h3 = __float2bfloat16_rn(xv.w);
            uint32_t hA = ((uint32_t)*(uint16_t*)&h1 << 16) | *(uint16_t*)&h0;
            uint32_t hB = ((uint32_t)*(uint16_t*)&h3 << 16) | *(uint16_t*)&h2;
            uint32_t lA = pack_bf2(xv.x - __bfloat162float(h0), xv.y - __bfloat162float(h1));
            uint32_t lB = pack_bf2(xv.z - __bfloat162float(h2), xv.w - __bfloat162float(h3));
            *(uint2*)(sm + QK_XH + c * XP + n * 2) = make_uint2(hA, hB);
            *(uint2*)(sm + QK_XL + c * XP + n * 2) = make_uint2(lA, lB);
        }
        #pragma unroll
        for (int w = 0; w < 3; ++w) {
            const float* W = Wp[w];
            #pragma unroll
            for (int r = 0; r < 4; ++r) {
                int idx = r * 256 + tid;
                int o = idx >> 4, f4 = idx & 15;
                int c = f4 * 4;
                float4 wv = *(const float4*)&W[(size_t)o * CIN + kc + c];
                __nv_bfloat16 h0 = __float2bfloat16_rn(wv.x);
                __nv_bfloat16 h1 = __float2bfloat16_rn(wv.y);
                __nv_bfloat16 h2 = __float2bfloat16_rn(wv.z);
                __nv_bfloat16 h3 = __float2bfloat16_rn(wv.w);
                uint32_t hA = ((uint32_t)*(uint16_t*)&h1 << 16) | *(uint16_t*)&h0;
                uint32_t hB = ((uint32_t)*(uint16_t*)&h3 << 16) | *(uint16_t*)&h2;
                uint32_t lA = pack_bf2(wv.x - __bfloat162float(h0), wv.y - __bfloat162float(h1));
                uint32_t lB = pack_bf2(wv.z - __bfloat162float(h2), wv.w - __bfloat162float(h3));
                *(uint2*)(sm + QK_W + w * 18432 + o * WP + c * 2) = make_uint2(hA, hB);
                *(uint2*)(sm + QK_W + w * 18432 + 9216 + o * WP + c * 2) = make_uint2(lA, lB);
            }
        }
        __syncthreads();

        #pragma unroll
        for (int kt = 0; kt < 4; ++kt) {
            uint32_t ah[4], al[4];
            LDSM4T(ah, aX + kt * 16 * XP);
            LDSM4T(al, aXl + kt * 16 * XP);
            #pragma unroll
            for (int w = 0; w < 3; ++w) {
                const uint32_t aW  = aW0 + w * 18432;
                const uint32_t aWl = aW + 9216;
                #pragma unroll
                for (int p = 0; p < 4; ++p) {
                    uint32_t bh[4], bl[4];
                    LDSM4(bh, aW + p * 16 * WP + kt * 32);
                    LDSM4(bl, aWl + p * 16 * WP + kt * 32);
                    float* d0 = d[w][2 * p];
                    float* d1 = d[w][2 * p + 1];
                    mma_bf16(d0, ah, bh[0], bh[1]);
                    mma_bf16(d1, ah, bh[2], bh[3]);
                    mma_bf16(d0, ah, bl[0], bl[1]);
                    mma_bf16(d1, ah, bl[2], bl[3]);
                    mma_bf16(d0, al, bh[0], bh[1]);
                    mma_bf16(d1, al, bh[2], bh[3]);
                }
            }
        }
    }

    #pragma unroll
    for (int w = 0; w < 3; ++w) {
        if (w < 2) {
            __nv_bfloat16* dh = (w == 0) ? g_ft_h : g_gt_h;
            __nv_bfloat16* dl = (w == 0) ? g_ft_l : g_gt_l;
            #pragma unroll
            for (int ot = 0; ot < 8; ++ot) {
                int o = ot * 8 + 2 * tg;
                int n_a = n0 + wid * 16 + g;
                size_t base_a = ((size_t)b * NN + n_a) * C8 + o;
                size_t base_b = base_a + 8 * C8;
                float v0 = d[w][ot][0], v1 = d[w][ot][1], v2 = d[w][ot][2], v3 = d[w][ot][3];
                __nv_bfloat16 h0 = __float2bfloat16_rn(v0);
                __nv_bfloat16 h1 = __float2bfloat16_rn(v1);
                __nv_bfloat16 h2 = __float2bfloat16_rn(v2);
                __nv_bfloat16 h3 = __float2bfloat16_rn(v3);
                *(uint32_t*)&dh[base_a] = ((uint32_t)*(uint16_t*)&h1 << 16) | *(uint16_t*)&h0;
                *(uint32_t*)&dh[base_b] = ((uint32_t)*(uint16_t*)&h3 << 16) | *(uint16_t*)&h2;
                *(uint32_t*)&dl[base_a] = pack_bf2(v0 - __bfloat162float(h0), v1 - __bfloat162float(h1));
                *(uint32_t*)&dl[base_b] = pack_bf2(v2 - __bfloat162float(h2), v3 - __bfloat162float(h3));
            }
        } else {
            #pragma unroll
            for (int ot = 0; ot < 8; ++ot) {
                int o = ot * 8 + 2 * tg;
                int n_a = n0 + wid * 16 + g;
                #pragma unroll
                for (int e = 0; e < 2; ++e) {
                    #pragma unroll
                    for (int rr = 0; rr < 2; ++rr) {
                        float v = d[w][ot][rr * 2 + e];
                        size_t idx = ((size_t)b * C8 + o + e) * NN + n_a + rr * 8;
                        __nv_bfloat16 h = __float2bfloat16_rn(v);
                        g_h_h[idx] = h;
                        g_h_l[idx] = __float2bfloat16_rn(v - __bfloat162float(h));
                    }
                }
            }
        }
    }
}

// ---------------------------------------------------------------------------
// Kernel 2: flash attention (R13 loop) + FUSED output projection epilogue.
// After the loop: ao(c64,j128) = O/l as split-bf16 smem tile; stage Wv
// (preconverted bf16) via cp.async; sa = Wv·ao on mma; out = sa*gamma + x.
// ---------------------------------------------------------------------------
#define AQ_PITCH 144
#define AT_QH 0
#define AT_QL 18432
#define AT_KV 36864            // + cbuf*73728 ; tile: KH 0, KL 9216, VH 18432, VL 27648
// epilogue overlays (dead loop regions):
#define EP_OSM 0               // [4 wi][64 c][128 j] fp32 (128 KB)
#define EP_RED 131072
#define EP_LINV 133120
#define EP_WV  0               // 2 chunks x (36864 hi + 36864 lo) = 147456
#define EP_AOH 147456          // 64 x 272 = 17408
#define EP_AOL 164864
#define SMEM_ATTN 184320

__global__ __launch_bounds__(512, 1) void attn_kernel(const float* __restrict__ x,
                                                      const float* __restrict__ gammap,
                                                      float* __restrict__ out) {
    extern __shared__ char sm[];
    const uint32_t sb = smem_u32(sm);
    const int tid = threadIdx.x, wid = tid >> 5, lane = tid & 31;
    const int g = lane >> 2, tg = lane & 3;
    const int wi = wid & 3, wj = wid >> 2;
    const int j0 = blockIdx.x * 128;
    const int b  = blockIdx.y;

    const uint4* kh_g = (const uint4*)(g_ft_h + (size_t)b * NN * C8);
    const uint4* kl_g = (const uint4*)(g_ft_l + (size_t)b * NN * C8);
    const uint4* vh_g = (const uint4*)(g_h_h + (size_t)b * C8 * NN);
    const uint4* vl_g = (const uint4*)(g_h_l + (size_t)b * C8 * NN);

    {   // stage Q tile (128 j x 64 c, hi/lo) — resident
        const uint4* qh = (const uint4*)(g_gt_h + ((size_t)b * NN + j0) * C8);
        const uint4* ql = (const uint4*)(g_gt_l + ((size_t)b * NN + j0) * C8);
        #pragma unroll
        for (int r = 0; r < 2; ++r) {
            int u = r * 512 + tid;
            int row = u >> 3, q = u & 7;
            *(uint4*)(sm + AT_QH + row * AQ_PITCH + q * 16) = qh[row * 8 + q];
            *(uint4*)(sm + AT_QL + row * AQ_PITCH + q * 16) = ql[row * 8 + q];
        }
    }

    const uint32_t offK = (wi * 16 + (lane & 15)) * AQ_PITCH + ((lane >> 4) & 1) * 16;
    const uint32_t offV0 = 18432 + (lane & 15) * AQ_PITCH + wi * 32 + ((lane >> 4) & 1) * 16;
    const uint32_t b_row = ((lane >> 4) & 1) * 8 + (lane & 7);
    const uint32_t b_cb  = ((lane >> 3) & 1) * 16;
    uint32_t aQ[2], aQl[2];
    #pragma unroll
    for (int ntp = 0; ntp < 2; ++ntp) {
        aQ[ntp]  = sb + AT_QH + (wj * 32 + ntp * 16 + b_row) * AQ_PITCH + b_cb;
        aQl[ntp] = aQ[ntp] + (AT_QL - AT_QH);
    }

    auto stage_chunk = [&](int it2, int cbuf) {
        const uint32_t cb = sb + AT_KV + cbuf * 73728;
        int row = tid >> 3, q = tid & 7;
        #pragma unroll
        for (int sub = 0; sub < 2; ++sub) {
            const int i0 = it2 * 128 + sub * 64;
            uint32_t drow = cb + sub * 36864 + row * AQ_PITCH + q * 16;
            CP_ASYNC16(drow, kh_g + (size_t)(i0 + row) * 8 + q);
            CP_ASYNC16(drow + 9216, kl_g + (size_t)(i0 + row) * 8 + q);
            size_t vsrc = (size_t)row * (NN / 8) + (i0 >> 3) + q;
            CP_ASYNC16(drow + 18432, vh_g + vsrc);
            CP_ASYNC16(drow + 27648, vl_g + vsrc);
        }
    };

    stage_chunk(0, 0);
    CP_COMMIT();

    float o[16][4] = {};
    float ls[8] = {};

    for (int it2 = 0; it2 < 32; ++it2) {
        const int cbuf = it2 & 1;
        const uint32_t cb = sb + AT_KV + cbuf * 73728;
        CP_WAIT0();
        __syncthreads();

        float d[2][4][4] = {};
        #pragma unroll
        for (int kt = 0; kt < 4; ++kt) {
            uint32_t qh0[4], ql0[4], qh1[4], ql1[4];
            LDSM4(qh0, aQ[0] + kt * 32);
            LDSM4(ql0, aQl[0] + kt * 32);
            LDSM4(qh1, aQ[1] + kt * 32);
            LDSM4(ql1, aQl[1] + kt * 32);
            #pragma unroll
            for (int sub = 0; sub < 2; ++sub) {
                const uint32_t aK = cb + sub * 36864 + offK;
                uint32_t ah[4], al[4];
                LDSM4(ah, aK + kt * 32);
                LDSM4(al, aK + 9216 + kt * 32);
                float* d0 = d[sub][0];
                float* d1 = d[sub][1];
                float* d2 = d[sub][2];
                float* d3 = d[sub][3];
                mma_bf16(d0, ah, qh0[0], qh0[1]);
                mma_bf16(d1, ah, qh0[2], qh0[3]);
                mma_bf16(d2, ah, qh1[0], qh1[1]);
                mma_bf16(d3, ah, qh1[2], qh1[3]);
                mma_bf16(d0, ah, ql0[0], ql0[1]);
                mma_bf16(d1, ah, ql0[2], ql0[3]);
                mma_bf16(d2, ah, ql1[0], ql1[1]);
                mma_bf16(d3, ah, ql1[2], ql1[3]);
                mma_bf16(d0, al, qh0[0], qh0[1]);
                mma_bf16(d1, al, qh0[2], qh0[3]);
                mma_bf16(d2, al, qh1[0], qh1[1]);
                mma_bf16(d3, al, qh1[2], qh1[3]);
            }
        }

        if (it2 + 1 < 32) {
            stage_chunk(it2 + 1, cbuf ^ 1);
            CP_COMMIT();
        }

        #pragma unroll
        for (int sub = 0; sub < 2; ++sub) {
            uint32_t pb[4][4];
            #pragma unroll
            for (int nt = 0; nt < 4; ++nt) {
                float e0 = fast_exp(d[sub][nt][0]);
                float e1 = fast_exp(d[sub][nt][1]);
                float e2 = fast_exp(d[sub][nt][2]);
                float e3 = fast_exp(d[sub][nt][3]);
                ls[nt * 2]     += e0 + e2;
                ls[nt * 2 + 1] += e1 + e3;
                __nv_bfloat162 hA = __floats2bfloat162_rn(e0, e1);
                __nv_bfloat162 hB = __floats2bfloat162_rn(e2, e3);
                uint32_t uhA, uhB; memcpy(&uhA, &hA, 4); memcpy(&uhB, &hB, 4);
                uint32_t ulA = pack_bf2(e0 - __bfloat162float(hA.x), e1 - __bfloat162float(hA.y));
                uint32_t ulB = pack_bf2(e2 - __bfloat162float(hB.x), e3 - __bfloat162float(hB.y));
                MOVMAT(pb[nt][0], uhA);
                MOVMAT(pb[nt][1], uhB);
                MOVMAT(pb[nt][2], ulA);
                MOVMAT(pb[nt][3], ulB);
            }
            #pragma unroll
            for (int ct = 0; ct < 4; ++ct) {
                uint32_t vh[4], vl[4];
                uint32_t aV = cb + sub * 36864 + offV0 + ct * (16 * AQ_PITCH);
                LDSM4(vh, aV);
                LDSM4(vl, aV + 9216);
                #pragma unroll
                for (int nt = 0; nt < 4; ++nt) {
                    float* oo = o[ct * 4 + nt];
                    mma_bf16(oo, vh, pb[nt][0], pb[nt][1]);
                    mma_bf16(oo, vh, pb[nt][2], pb[nt][3]);
                    mma_bf16(oo, vl, pb[nt][0], pb[nt][1]);
                }
            }
        }
    }

    __syncthreads();   // loop done; Q/KV smem dead

    // ---- O partials -> Osm ; ls -> red ----
    float* Osm = (float*)(sm + EP_OSM);
    #pragma unroll
    for (int ct = 0; ct < 4; ++ct) {
        #pragma unroll
        for (int nt = 0; nt < 4; ++nt) {
            int c = ct * 16 + g;
            int jc = wj * 32 + nt * 8 + 2 * tg;
            float* os = Osm + ((size_t)wi * 64 + c) * 128 + jc;
            os[0] = o[ct * 4 + nt][0];
            os[1] = o[ct * 4 + nt][1];
            os[8 * 128] = o[ct * 4 + nt][2];
            os[8 * 128 + 1] = o[ct * 4 + nt][3];
        }
    }
    float* red = (float*)(sm + EP_RED);
    #pragma unroll
    for (int nt = 0; nt < 4; ++nt) {
        #pragma unroll
        for (int e = 0; e < 2; ++e) {
            float v = ls[nt * 2 + e];
            v += __shfl_down_sync(0xffffffffu, v, 4);
            v += __shfl_down_sync(0xffffffffu, v, 8);
            v += __shfl_down_sync(0xffffffffu, v, 16);
            if (lane < 4)
                red[wi * 128 + wj * 32 + nt * 8 + 2 * lane + e] = v;
        }
    }
    __syncthreads();

    float* linv = (float*)(sm + EP_LINV);
    if (tid < 128)
        linv[tid] = 1.0f / (red[tid] + red[128 + tid] + red[256 + tid] + red[384 + tid]);
    __syncthreads();

    // ---- build split-bf16 ao(c64, j128) tile ----
    {
        const int j = tid & 127;
        const int cg = tid >> 7;
        float inv = linv[j];
        #pragma unroll
        for (int k = 0; k < 16; ++k) {
            int c = cg * 16 + k;
            float v = (Osm[(size_t)c * 128 + j]
                     + Osm[(size_t)(64 + c) * 128 + j]
                     + Osm[(size_t)(128 + c) * 128 + j]
                     + Osm[(size_t)(192 + c) * 128 + j]) * inv;
            __nv_bfloat16 h = __float2bfloat16_rn(v);
            *(__nv_bfloat16*)(sm + EP_AOH + c * 272 + j * 2) = h;
            *(__nv_bfloat16*)(sm + EP_AOL + c * 272 + j * 2) =
                __float2bfloat16_rn(v - __bfloat162float(h));
        }
    }
    __syncthreads();   // Osm/red/linv consumed; EP_WV region free

    // ---- stage Wv (both 256-row chunks, hi/lo) via cp.async ----
    #pragma unroll
    for (int r = 0; r < 4; ++r) {
        int idx = r * 512 + tid;
        int row = idx >> 3, seg = idx & 7;
        #pragma unroll
        for (int ch = 0; ch < 2; ++ch) {
            uint32_t dst = sb + EP_WV + ch * 73728 + row * 144 + seg * 16;
            size_t srcI = ((size_t)(ch * 256 + row)) * C8 + seg * 8;
            CP_ASYNC16(dst, (const char*)g_wv_h + srcI * 2);
            CP_ASYNC16(dst + 36864, (const char*)g_wv_l + srcI * 2);
        }
    }
    CP_COMMIT();
    CP_WAIT0();
    __syncthreads();

    // ---- sa(m512, j128) = Wv · ao ; out = sa*gamma + x ----
    const float gamma = gammap[0];
    float* outSA = out + (size_t)NB * CIN * NN;
    const uint32_t aoB = sb + EP_AOH +
        (((lane >> 3) & 1) * 8 + (lane & 7)) * 272 + ((lane >> 4) & 1) * 16;
    #pragma unroll
    for (int p = 0; p < 2; ++p) {
        const int m0 = p * 256 + wid * 16;
        const uint32_t aWv = sb + EP_WV + p * 73728 +
            (wid * 16 + (lane & 15)) * 144 + ((lane >> 4) & 1) * 16;
        float dd[16][4] = {};
        #pragma unroll
        for (int kt = 0; kt < 4; ++kt) {
            uint32_t ah[4], al[4];
            LDSM4(ah, aWv + kt * 32);
            LDSM4(al, aWv + 36864 + kt * 32);
            #pragma unroll
            for (int jb = 0; jb < 8; ++jb) {
                uint32_t bh[4], bl[4];
                LDSM4T(bh, aoB + kt * (16 * 272) + jb * 32);
                LDSM4T(bl, aoB + (EP_AOL - EP_AOH) + kt * (16 * 272) + jb * 32);
                float* d0 = dd[jb * 2];
                float* d1 = dd[jb * 2 + 1];
                mma_bf16(d0, ah, bh[0], bh[1]);
                mma_bf16(d1, ah, bh[2], bh[3]);
                mma_bf16(d0, ah, bl[0], bl[1]);
                mma_bf16(d1, ah, bl[2], bl[3]);
                mma_bf16(d0, al, bh[0], bh[1]);
                mma_bf16(d1, al, bh[2], bh[3]);
            }
        }
        #pragma unroll
        for (int jt = 0; jt < 16; ++jt) {
            int jc = j0 + jt * 8 + 2 * tg;
            #pragma unroll
            for (int rr = 0; rr < 2; ++rr) {
                int m = m0 + g + rr * 8;
                size_t base = ((size_t)b * CIN + m) * NN + jc;
                float s0 = dd[jt][rr * 2], s1 = dd[jt][rr * 2 + 1];
                float2 xv = *(const float2*)&x[base];
                *(float2*)&outSA[base] = make_float2(s0, s1);
                *(float2*)&out[base] =
                    make_float2(fmaf(s0, gamma, xv.x), fmaf(s1, gamma, xv.y));
            }
        }
    }
}

extern "C" void kernel_launch(void* const* d_in, const int* in_sizes, int n_in,
                              void* d_out, int out_size) {
    const float* x     = (const float*)d_in[0];
    const float* Wf    = (const float*)d_in[1];
    const float* Wg    = (const float*)d_in[2];
    const float* Wh    = (const float*)d_in[3];
    const float* Wv    = (const float*)d_in[4];
    const float* gamma = (const float*)d_in[5];
    float* out = (float*)d_out;

    cudaFuncSetAttribute(qkv_kernel,
                         cudaFuncAttributeMaxDynamicSharedMemorySize, SMEM_QKV);
    cudaFuncSetAttribute(attn_kernel,
                         cudaFuncAttributeMaxDynamicSharedMemorySize, SMEM_ATTN);

    wvconv_kernel<<<128, 256>>>(Wv);
    qkv_kernel<<<dim3(32, 4), 256, SMEM_QKV>>>(x, Wf, Wg, Wh);
    attn_kernel<<<dim3(32, 4), 512, SMEM_ATTN>>>(x, gamma, out);
}

// round 16
// speedup vs baseline: 1.1014x; 1.1014x over previous
#include <cuda_runtime.h>
#include <cuda_bf16.h>
#include <cstdint>
#include <cstring>

#define NB 4
#define CIN 512
#define C8 64
#define NN 4096

// ---------------- scratch (static; no allocs allowed) ----------------
__device__ __align__(16) __nv_bfloat16 g_ft_h[NB * NN * C8];
__device__ __align__(16) __nv_bfloat16 g_ft_l[NB * NN * C8];
__device__ __align__(16) __nv_bfloat16 g_gt_h[NB * NN * C8];
__device__ __align__(16) __nv_bfloat16 g_gt_l[NB * NN * C8];
__device__ __align__(16) __nv_bfloat16 g_h_h[NB * C8 * NN];
__device__ __align__(16) __nv_bfloat16 g_h_l[NB * C8 * NN];
__device__ __align__(16) __nv_bfloat16 g_wv_h[CIN * C8];
__device__ __align__(16) __nv_bfloat16 g_wv_l[CIN * C8];
__device__ __align__(16) __nv_bfloat16 g_ao_h[NB * C8 * NN];
__device__ __align__(16) __nv_bfloat16 g_ao_l[NB * C8 * NN];

// ---------------- helpers ----------------
__device__ __forceinline__ uint32_t smem_u32(const void* p) {
    uint32_t a;
    asm("{ .reg .u64 t; cvta.to.shared.u64 t, %1; cvt.u32.u64 %0, t; }" : "=r"(a) : "l"(p));
    return a;
}

__device__ __forceinline__ float fast_exp(float x) {
    float t = fmaxf(x * 1.4426950408889634f, -126.0f);
    float fi = floorf(t);
    float r = t - fi;
    float p =       1.5403530e-4f;
    p = fmaf(p, r,  1.3333558e-3f);
    p = fmaf(p, r,  9.6181291e-3f);
    p = fmaf(p, r,  5.5504109e-2f);
    p = fmaf(p, r,  2.4022651e-1f);
    p = fmaf(p, r,  6.9314718e-1f);
    p = fmaf(p, r,  1.0f);
    return __int_as_float(((int)fi + 127) << 23) * p;
}

// sm_75/80-era ops — legal on EVERY compilation pass.
#define LDSM4(r, a) \
    asm volatile("ldmatrix.sync.aligned.m8n8.x4.shared.b16 {%0,%1,%2,%3},[%4];" \
        : "=r"((r)[0]), "=r"((r)[1]), "=r"((r)[2]), "=r"((r)[3]) : "r"(a))
#define LDSM4T(r, a) \
    asm volatile("ldmatrix.sync.aligned.m8n8.x4.trans.shared.b16 {%0,%1,%2,%3},[%4];" \
        : "=r"((r)[0]), "=r"((r)[1]), "=r"((r)[2]), "=r"((r)[3]) : "r"(a))
#define MOVMAT(d, s) \
    asm volatile("movmatrix.sync.aligned.m8n8.trans.b16 %0, %1;" : "=r"(d) : "r"(s))
#define CP_ASYNC16(dst, src) \
    asm volatile("cp.async.cg.shared.global [%0], [%1], 16;" :: "r"(dst), "l"(src))
#define CP_COMMIT() asm volatile("cp.async.commit_group;" ::: "memory")
#define CP_WAIT0()  asm volatile("cp.async.wait_group 0;" ::: "memory")

__device__ __forceinline__ void mma_bf16(float* d, const uint32_t* a, uint32_t b0, uint32_t b1) {
    asm volatile("mma.sync.aligned.m16n8k16.row.col.f32.bf16.bf16.f32 "
                 "{%0,%1,%2,%3},{%4,%5,%6,%7},{%8,%9},{%0,%1,%2,%3};"
                 : "+f"(d[0]), "+f"(d[1]), "+f"(d[2]), "+f"(d[3])
                 : "r"(a[0]), "r"(a[1]), "r"(a[2]), "r"(a[3]), "r"(b0), "r"(b1));
}

__device__ __forceinline__ uint32_t pack_bf2(float a, float b) {
    __nv_bfloat162 h2 = __floats2bfloat162_rn(a, b);
    uint32_t u; memcpy(&u, &h2, 4); return u;
}

// ---------------------------------------------------------------------------
// Kernel 0: convert Wv fp32 -> split-bf16 (read 128x by proj).
// ---------------------------------------------------------------------------
__global__ void wvconv_kernel(const float* __restrict__ Wv) {
    int idx = blockIdx.x * 256 + threadIdx.x;
    if (idx >= CIN * C8) return;
    float v = Wv[idx];
    __nv_bfloat16 h = __float2bfloat16_rn(v);
    g_wv_h[idx] = h;
    g_wv_l[idx] = __float2bfloat16_rn(v - __bfloat162float(h));
}

// ---------------------------------------------------------------------------
// Kernel 1: QKV — R13 version (proven 52.7us). UNCHANGED.
// ---------------------------------------------------------------------------
#define XP 272
#define WP 144
#define QK_XH 0
#define QK_XL 17408
#define QK_W  34816
#define SMEM_QKV 90112

__global__ __launch_bounds__(256) void qkv_kernel(const float* __restrict__ x,
                                                  const float* __restrict__ Wf,
                                                  const float* __restrict__ Wg,
                                                  const float* __restrict__ Wh) {
    extern __shared__ char sm[];
    const uint32_t sb = smem_u32(sm);
    const int tid = threadIdx.x, wid = tid >> 5, lane = tid & 31;
    const int g = lane >> 2, tg = lane & 3;
    const int n0 = blockIdx.x * 128;
    const int b  = blockIdx.y;
    const float* xb = x + (size_t)b * CIN * NN;
    const float* Wp[3] = { Wf, Wg, Wh };

    const uint32_t at_row = (lane & 7) + ((lane >> 4) & 1) * 8;
    const uint32_t at_cb  = ((lane >> 3) & 1) * 16;
    const uint32_t aX  = sb + QK_XH + at_row * XP + wid * 32 + at_cb;
    const uint32_t aXl = aX + (QK_XL - QK_XH);
    const uint32_t b_row = ((lane >> 4) & 1) * 8 + (lane & 7);
    const uint32_t b_cb  = ((lane >> 3) & 1) * 16;
    const uint32_t aW0 = sb + QK_W + b_row * WP + b_cb;

    float d[3][8][4] = {};

    for (int kci = 0; kci < 8; ++kci) {
        const int kc = kci * 64;
        __syncthreads();
        #pragma unroll
        for (int r = 0; r < 8; ++r) {
            int idx = r * 256 + tid;
            int c = idx >> 5, f4 = idx & 31;
            int n = f4 * 4;
            float4 xv = *(const float4*)&xb[(size_t)(kc + c) * NN + n0 + n];
            __nv_bfloat16 h0 = __float2bfloat16_rn(xv.x);
            __nv_bfloat16 h1 = __float2bfloat16_rn(xv.y);
            __nv_bfloat16 h2 = __float2bfloat16_rn(xv.z);
            __nv_bfloat16 h3 = __float2bfloat16_rn(xv.w);
            uint32_t hA = ((uint32_t)*(uint16_t*)&h1 << 16) | *(uint16_t*)&h0;
            uint32_t hB = ((uint32_t)*(uint16_t*)&h3 << 16) | *(uint16_t*)&h2;
            uint32_t lA = pack_bf2(xv.x - __bfloat162float(h0), xv.y - __bfloat162float(h1));
            uint32_t lB = pack_bf2(xv.z - __bfloat162float(h2), xv.w - __bfloat162float(h3));
            *(uint2*)(sm + QK_XH + c * XP + n * 2) = make_uint2(hA, hB);
            *(uint2*)(sm + QK_XL + c * XP + n * 2) = make_uint2(lA, lB);
        }
        #pragma unroll
        for (int w = 0; w < 3; ++w) {
            const float* W = Wp[w];
            #pragma unroll
            for (int r = 0; r < 4; ++r) {
                int idx = r * 256 + tid;
                int o = idx >> 4, f4 = idx & 15;
                int c = f4 * 4;
                float4 wv = *(const float4*)&W[(size_t)o * CIN + kc + c];
                __nv_bfloat16 h0 = __float2bfloat16_rn(wv.x);
                __nv_bfloat16 h1 = __float2bfloat16_rn(wv.y);
                __nv_bfloat16 h2 = __float2bfloat16_rn(wv.z);
                __nv_bfloat16 h3 = __float2bfloat16_rn(wv.w);
                uint32_t hA = ((uint32_t)*(uint16_t*)&h1 << 16) | *(uint16_t*)&h0;
                uint32_t hB = ((uint32_t)*(uint16_t*)&h3 << 16) | *(uint16_t*)&h2;
                uint32_t lA = pack_bf2(wv.x - __bfloat162float(h0), wv.y - __bfloat162float(h1));
                uint32_t lB = pack_bf2(wv.z - __bfloat162float(h2), wv.w - __bfloat162float(h3));
                *(uint2*)(sm + QK_W + w * 18432 + o * WP + c * 2) = make_uint2(hA, hB);
                *(uint2*)(sm + QK_W + w * 18432 + 9216 + o * WP + c * 2) = make_uint2(lA, lB);
            }
        }
        __syncthreads();

        #pragma unroll
        for (int kt = 0; kt < 4; ++kt) {
            uint32_t ah[4], al[4];
            LDSM4T(ah, aX + kt * 16 * XP);
            LDSM4T(al, aXl + kt * 16 * XP);
            #pragma unroll
            for (int w = 0; w < 3; ++w) {
                const uint32_t aW  = aW0 + w * 18432;
                const uint32_t aWl = aW + 9216;
                #pragma unroll
                for (int p = 0; p < 4; ++p) {
                    uint32_t bh[4], bl[4];
                    LDSM4(bh, aW + p * 16 * WP + kt * 32);
                    LDSM4(bl, aWl + p * 16 * WP + kt * 32);
                    float* d0 = d[w][2 * p];
                    float* d1 = d[w][2 * p + 1];
                    mma_bf16(d0, ah, bh[0], bh[1]);
                    mma_bf16(d1, ah, bh[2], bh[3]);
                    mma_bf16(d0, ah, bl[0], bl[1]);
                    mma_bf16(d1, ah, bl[2], bl[3]);
                    mma_bf16(d0, al, bh[0], bh[1]);
                    mma_bf16(d1, al, bh[2], bh[3]);
                }
            }
        }
    }

    #pragma unroll
    for (int w = 0; w < 3; ++w) {
        if (w < 2) {
            __nv_bfloat16* dh = (w == 0) ? g_ft_h : g_gt_h;
            __nv_bfloat16* dl = (w == 0) ? g_ft_l : g_gt_l;
            #pragma unroll
            for (int ot = 0; ot < 8; ++ot) {
                int o = ot * 8 + 2 * tg;
                int n_a = n0 + wid * 16 + g;
                size_t base_a = ((size_t)b * NN + n_a) * C8 + o;
                size_t base_b = base_a + 8 * C8;
                float v0 = d[w][ot][0], v1 = d[w][ot][1], v2 = d[w][ot][2], v3 = d[w][ot][3];
                __nv_bfloat16 h0 = __float2bfloat16_rn(v0);
                __nv_bfloat16 h1 = __float2bfloat16_rn(v1);
                __nv_bfloat16 h2 = __float2bfloat16_rn(v2);
                __nv_bfloat16 h3 = __float2bfloat16_rn(v3);
                *(uint32_t*)&dh[base_a] = ((uint32_t)*(uint16_t*)&h1 << 16) | *(uint16_t*)&h0;
                *(uint32_t*)&dh[base_b] = ((uint32_t)*(uint16_t*)&h3 << 16) | *(uint16_t*)&h2;
                *(uint32_t*)&dl[base_a] = pack_bf2(v0 - __bfloat162float(h0), v1 - __bfloat162float(h1));
                *(uint32_t*)&dl[base_b] = pack_bf2(v2 - __bfloat162float(h2), v3 - __bfloat162float(h3));
            }
        } else {
            #pragma unroll
            for (int ot = 0; ot < 8; ++ot) {
                int o = ot * 8 + 2 * tg;
                int n_a = n0 + wid * 16 + g;
                #pragma unroll
                for (int e = 0; e < 2; ++e) {
                    #pragma unroll
                    for (int rr = 0; rr < 2; ++rr) {
                        float v = d[w][ot][rr * 2 + e];
                        size_t idx = ((size_t)b * C8 + o + e) * NN + n_a + rr * 8;
                        __nv_bfloat16 h = __float2bfloat16_rn(v);
                        g_h_h[idx] = h;
                        g_h_l[idx] = __float2bfloat16_rn(v - __bfloat162float(h));
                    }
                }
            }
        }
    }
}

// ---------------------------------------------------------------------------
// Kernel 2: flash attention — R13 loop UNCHANGED; epilogue writes split-bf16 ao.
// ---------------------------------------------------------------------------
#define AQ_PITCH 144
#define AT_QH 0
#define AT_QL 18432
#define AT_KV 36864
#define AT_OSM 0
#define AT_RED 131072
#define AT_LINV 133120
#define SMEM_ATTN 184320

__global__ __launch_bounds__(512, 1) void attn_kernel() {
    extern __shared__ char sm[];
    const uint32_t sb = smem_u32(sm);
    const int tid = threadIdx.x, wid = tid >> 5, lane = tid & 31;
    const int g = lane >> 2, tg = lane & 3;
    const int wi = wid & 3, wj = wid >> 2;
    const int j0 = blockIdx.x * 128;
    const int b  = blockIdx.y;

    const uint4* kh_g = (const uint4*)(g_ft_h + (size_t)b * NN * C8);
    const uint4* kl_g = (const uint4*)(g_ft_l + (size_t)b * NN * C8);
    const uint4* vh_g = (const uint4*)(g_h_h + (size_t)b * C8 * NN);
    const uint4* vl_g = (const uint4*)(g_h_l + (size_t)b * C8 * NN);

    {
        const uint4* qh = (const uint4*)(g_gt_h + ((size_t)b * NN + j0) * C8);
        const uint4* ql = (const uint4*)(g_gt_l + ((size_t)b * NN + j0) * C8);
        #pragma unroll
        for (int r = 0; r < 2; ++r) {
            int u = r * 512 + tid;
            int row = u >> 3, q = u & 7;
            *(uint4*)(sm + AT_QH + row * AQ_PITCH + q * 16) = qh[row * 8 + q];
            *(uint4*)(sm + AT_QL + row * AQ_PITCH + q * 16) = ql[row * 8 + q];
        }
    }

    const uint32_t offK = (wi * 16 + (lane & 15)) * AQ_PITCH + ((lane >> 4) & 1) * 16;
    const uint32_t offV0 = 18432 + (lane & 15) * AQ_PITCH + wi * 32 + ((lane >> 4) & 1) * 16;
    const uint32_t b_row = ((lane >> 4) & 1) * 8 + (lane & 7);
    const uint32_t b_cb  = ((lane >> 3) & 1) * 16;
    uint32_t aQ[2], aQl[2];
    #pragma unroll
    for (int ntp = 0; ntp < 2; ++ntp) {
        aQ[ntp]  = sb + AT_QH + (wj * 32 + ntp * 16 + b_row) * AQ_PITCH + b_cb;
        aQl[ntp] = aQ[ntp] + (AT_QL - AT_QH);
    }

    auto stage_chunk = [&](int it2, int cbuf) {
        const uint32_t cb = sb + AT_KV + cbuf * 73728;
        int row = tid >> 3, q = tid & 7;
        #pragma unroll
        for (int sub = 0; sub < 2; ++sub) {
            const int i0 = it2 * 128 + sub * 64;
            uint32_t drow = cb + sub * 36864 + row * AQ_PITCH + q * 16;
            CP_ASYNC16(drow, kh_g + (size_t)(i0 + row) * 8 + q);
            CP_ASYNC16(drow + 9216, kl_g + (size_t)(i0 + row) * 8 + q);
            size_t vsrc = (size_t)row * (NN / 8) + (i0 >> 3) + q;
            CP_ASYNC16(drow + 18432, vh_g + vsrc);
            CP_ASYNC16(drow + 27648, vl_g + vsrc);
        }
    };

    stage_chunk(0, 0);
    CP_COMMIT();

    float o[16][4] = {};
    float ls[8] = {};

    for (int it2 = 0; it2 < 32; ++it2) {
        const int cbuf = it2 & 1;
        const uint32_t cb = sb + AT_KV + cbuf * 73728;
        CP_WAIT0();
        __syncthreads();

        float d[2][4][4] = {};
        #pragma unroll
        for (int kt = 0; kt < 4; ++kt) {
            uint32_t qh0[4], ql0[4], qh1[4], ql1[4];
            LDSM4(qh0, aQ[0] + kt * 32);
            LDSM4(ql0, aQl[0] + kt * 32);
            LDSM4(qh1, aQ[1] + kt * 32);
            LDSM4(ql1, aQl[1] + kt * 32);
            #pragma unroll
            for (int sub = 0; sub < 2; ++sub) {
                const uint32_t aK = cb + sub * 36864 + offK;
                uint32_t ah[4], al[4];
                LDSM4(ah, aK + kt * 32);
                LDSM4(al, aK + 9216 + kt * 32);
                float* d0 = d[sub][0];
                float* d1 = d[sub][1];
                float* d2 = d[sub][2];
                float* d3 = d[sub][3];
                mma_bf16(d0, ah, qh0[0], qh0[1]);
                mma_bf16(d1, ah, qh0[2], qh0[3]);
                mma_bf16(d2, ah, qh1[0], qh1[1]);
                mma_bf16(d3, ah, qh1[2], qh1[3]);
                mma_bf16(d0, ah, ql0[0], ql0[1]);
                mma_bf16(d1, ah, ql0[2], ql0[3]);
                mma_bf16(d2, ah, ql1[0], ql1[1]);
                mma_bf16(d3, ah, ql1[2], ql1[3]);
                mma_bf16(d0, al, qh0[0], qh0[1]);
                mma_bf16(d1, al, qh0[2], qh0[3]);
                mma_bf16(d2, al, qh1[0], qh1[1]);
                mma_bf16(d3, al, qh1[2], qh1[3]);
            }
        }

        if (it2 + 1 < 32) {
            stage_chunk(it2 + 1, cbuf ^ 1);
            CP_COMMIT();
        }

        #pragma unroll
        for (int sub = 0; sub < 2; ++sub) {
            uint32_t pb[4][4];
            #pragma unroll
            for (int nt = 0; nt < 4; ++nt) {
                float e0 = fast_exp(d[sub][nt][0]);
                float e1 = fast_exp(d[sub][nt][1]);
                float e2 = fast_exp(d[sub][nt][2]);
                float e3 = fast_exp(d[sub][nt][3]);
                ls[nt * 2]     += e0 + e2;
                ls[nt * 2 + 1] += e1 + e3;
                __nv_bfloat162 hA = __floats2bfloat162_rn(e0, e1);
                __nv_bfloat162 hB = __floats2bfloat162_rn(e2, e3);
                uint32_t uhA, uhB; memcpy(&uhA, &hA, 4); memcpy(&uhB, &hB, 4);
                uint32_t ulA = pack_bf2(e0 - __bfloat162float(hA.x), e1 - __bfloat162float(hA.y));
                uint32_t ulB = pack_bf2(e2 - __bfloat162float(hB.x), e3 - __bfloat162float(hB.y));
                MOVMAT(pb[nt][0], uhA);
                MOVMAT(pb[nt][1], uhB);
                MOVMAT(pb[nt][2], ulA);
                MOVMAT(pb[nt][3], ulB);
            }
            #pragma unroll
            for (int ct = 0; ct < 4; ++ct) {
                uint32_t vh[4], vl[4];
                uint32_t aV = cb + sub * 36864 + offV0 + ct * (16 * AQ_PITCH);
                LDSM4(vh, aV);
                LDSM4(vl, aV + 9216);
                #pragma unroll
                for (int nt = 0; nt < 4; ++nt) {
                    float* oo = o[ct * 4 + nt];
                    mma_bf16(oo, vh, pb[nt][0], pb[nt][1]);
                    mma_bf16(oo, vh, pb[nt][2], pb[nt][3]);
                    mma_bf16(oo, vl, pb[nt][0], pb[nt][1]);
                }
            }
        }
    }

    __syncthreads();

    float* Osm = (float*)(sm + AT_OSM);
    #pragma unroll
    for (int ct = 0; ct < 4; ++ct) {
        #pragma unroll
        for (int nt = 0; nt < 4; ++nt) {
            int c = ct * 16 + g;
            int jc = wj * 32 + nt * 8 + 2 * tg;
            float* os = Osm + ((size_t)wi * 64 + c) * 128 + jc;
            os[0] = o[ct * 4 + nt][0];
            os[1] = o[ct * 4 + nt][1];
            os[8 * 128] = o[ct * 4 + nt][2];
            os[8 * 128 + 1] = o[ct * 4 + nt][3];
        }
    }
    float* red = (float*)(sm + AT_RED);
    #pragma unroll
    for (int nt = 0; nt < 4; ++nt) {
        #pragma unroll
        for (int e = 0; e < 2; ++e) {
            float v = ls[nt * 2 + e];
            v += __shfl_down_sync(0xffffffffu, v, 4);
            v += __shfl_down_sync(0xffffffffu, v, 8);
            v += __shfl_down_sync(0xffffffffu, v, 16);
            if (lane < 4)
                red[wi * 128 + wj * 32 + nt * 8 + 2 * lane + e] = v;
        }
    }
    __syncthreads();

    float* linv = (float*)(sm + AT_LINV);
    if (tid < 128)
        linv[tid] = 1.0f / (red[tid] + red[128 + tid] + red[256 + tid] + red[384 + tid]);
    __syncthreads();

    {   // write ao as split-bf16 (proj consumes it on tensor cores)
        const int j = tid & 127;
        const int cg = tid >> 7;
        float inv = linv[j];
        size_t base = (size_t)b * C8 * NN + j0 + j;
        #pragma unroll
        for (int k = 0; k < 16; ++k) {
            int c = cg * 16 + k;
            float v = (Osm[(size_t)c * 128 + j]
                     + Osm[(size_t)(64 + c) * 128 + j]
                     + Osm[(size_t)(128 + c) * 128 + j]
                     + Osm[(size_t)(192 + c) * 128 + j]) * inv;
            __nv_bfloat16 h = __float2bfloat16_rn(v);
            g_ao_h[base + (size_t)c * NN] = h;
            g_ao_l[base + (size_t)c * NN] = __float2bfloat16_rn(v - __bfloat162float(h));
        }
    }
}

// ---------------------------------------------------------------------------
// Kernel 3: proj on mma.sync. sa(m512,j128) = Wv·ao ; out = sa*gamma + x.
// Grid (32 j-tiles, 4 b), 512 threads. Standalone -> clean register budget.
// ---------------------------------------------------------------------------
#define PR_WV 0                 // hi: row*144 (73728), lo: +73728
#define PR_AOH 147456           // 64 x 272
#define PR_AOL 164864
#define SMEM_PROJ 182272

__global__ __launch_bounds__(512, 1) void proj_kernel(const float* __restrict__ x,
                                                      const float* __restrict__ gammap,
                                                      float* __restrict__ out) {
    extern __shared__ char sm[];
    const uint32_t sb = smem_u32(sm);
    const int tid = threadIdx.x, wid = tid >> 5, lane = tid & 31;
    const int g = lane >> 2, tg = lane & 3;
    const int j0 = blockIdx.x * 128;
    const int b  = blockIdx.y;

    // stage Wv (512 x 64, hi/lo) and ao tile (64 x 128, hi/lo) via cp.async
    #pragma unroll
    for (int r = 0; r < 8; ++r) {
        int idx = r * 512 + tid;
        int row = idx >> 3, seg = idx & 7;
        uint32_t dst = sb + PR_WV + row * 144 + seg * 16;
        size_t srcI = (size_t)row * C8 + seg * 8;
        CP_ASYNC16(dst, (const char*)g_wv_h + srcI * 2);
        CP_ASYNC16(dst + 73728, (const char*)g_wv_l + srcI * 2);
    }
    #pragma unroll
    for (int r = 0; r < 2; ++r) {
        int idx = r * 512 + tid;
        int c = idx >> 4, seg = idx & 15;
        uint32_t dst = sb + PR_AOH + c * 272 + seg * 16;
        size_t srcI = ((size_t)b * C8 + c) * NN + j0 + seg * 8;
        CP_ASYNC16(dst, (const char*)g_ao_h + srcI * 2);
        CP_ASYNC16(dst + (PR_AOL - PR_AOH), (const char*)g_ao_l + srcI * 2);
    }
    CP_COMMIT();
    CP_WAIT0();
    __syncthreads();

    const float gamma = gammap[0];
    float* outSA = out + (size_t)NB * CIN * NN;
    const uint32_t aoB = sb + PR_AOH +
        (((lane >> 3) & 1) * 8 + (lane & 7)) * 272 + ((lane >> 4) & 1) * 16;

    #pragma unroll
    for (int p = 0; p < 2; ++p) {
        const int m0 = p * 256 + wid * 16;
        const uint32_t aWv = sb + PR_WV +
            (m0 + (lane & 15)) * 144 + ((lane >> 4) & 1) * 16;
        float dd[16][4] = {};
        #pragma unroll
        for (int kt = 0; kt < 4; ++kt) {
            uint32_t ah[4], al[4];
            LDSM4(ah, aWv + kt * 32);
            LDSM4(al, aWv + 73728 + kt * 32);
            #pragma unroll
            for (int jb = 0; jb < 8; ++jb) {
                uint32_t bh[4], bl[4];
                LDSM4T(bh, aoB + kt * (16 * 272) + jb * 32);
                LDSM4T(bl, aoB + (PR_AOL - PR_AOH) + kt * (16 * 272) + jb * 32);
                float* d0 = dd[jb * 2];
                float* d1 = dd[jb * 2 + 1];
                mma_bf16(d0, ah, bh[0], bh[1]);
                mma_bf16(d1, ah, bh[2], bh[3]);
                mma_bf16(d0, ah, bl[0], bl[1]);
                mma_bf16(d1, ah, bl[2], bl[3]);
                mma_bf16(d0, al, bh[0], bh[1]);
                mma_bf16(d1, al, bh[2], bh[3]);
            }
        }
        #pragma unroll
        for (int jt = 0; jt < 16; ++jt) {
            int jc = j0 + jt * 8 + 2 * tg;
            #pragma unroll
            for (int rr = 0; rr < 2; ++rr) {
                int m = m0 + g + rr * 8;
                size_t base = ((size_t)b * CIN + m) * NN + jc;
                float s0 = dd[jt][rr * 2], s1 = dd[jt][rr * 2 + 1];
                float2 xv = *(const float2*)&x[base];
                *(float2*)&outSA[base] = make_float2(s0, s1);
                *(float2*)&out[base] =
                    make_float2(fmaf(s0, gamma, xv.x), fmaf(s1, gamma, xv.y));
            }
        }
    }
}

extern "C" void kernel_launch(void* const* d_in, const int* in_sizes, int n_in,
                              void* d_out, int out_size) {
    const float* x     = (const float*)d_in[0];
    const float* Wf    = (const float*)d_in[1];
    const float* Wg    = (const float*)d_in[2];
    const float* Wh    = (const float*)d_in[3];
    const float* Wv    = (const float*)d_in[4];
    const float* gamma = (const float*)d_in[5];
    float* out = (float*)d_out;

    cudaFuncSetAttribute(qkv_kernel,
                         cudaFuncAttributeMaxDynamicSharedMemorySize, SMEM_QKV);
    cudaFuncSetAttribute(attn_kernel,
                         cudaFuncAttributeMaxDynamicSharedMemorySize, SMEM_ATTN);
    cudaFuncSetAttribute(proj_kernel,
                         cudaFuncAttributeMaxDynamicSharedMemorySize, SMEM_PROJ);

    wvconv_kernel<<<128, 256>>>(Wv);
    qkv_kernel<<<dim3(32, 4), 256, SMEM_QKV>>>(x, Wf, Wg, Wh);
    attn_kernel<<<dim3(32, 4), 512, SMEM_ATTN>>>();
    proj_kernel<<<dim3(32, 4), 512, SMEM_PROJ>>>(x, gamma, out);
}

// round 17
// speedup vs baseline: 1.1836x; 1.0746x over previous
#include <cuda_runtime.h>
#include <cuda_bf16.h>
#include <cstdint>
#include <cstring>

#define NB 4
#define CIN 512
#define C8 64
#define NN 4096

// ---------------- scratch (static; no allocs allowed) ----------------
__device__ __align__(16) __nv_bfloat16 g_ft_h[NB * NN * C8];
__device__ __align__(16) __nv_bfloat16 g_ft_l[NB * NN * C8];
__device__ __align__(16) __nv_bfloat16 g_gt_h[NB * NN * C8];
__device__ __align__(16) __nv_bfloat16 g_gt_l[NB * NN * C8];
__device__ __align__(16) __nv_bfloat16 g_h_h[NB * C8 * NN];
__device__ __align__(16) __nv_bfloat16 g_h_l[NB * C8 * NN];
__device__ __align__(16) __nv_bfloat16 g_wv_h[CIN * C8];
__device__ __align__(16) __nv_bfloat16 g_wv_l[CIN * C8];
__device__ __align__(16) __nv_bfloat16 g_ao_h[NB * C8 * NN];
__device__ __align__(16) __nv_bfloat16 g_ao_l[NB * C8 * NN];

// ---------------- helpers ----------------
__device__ __forceinline__ uint32_t smem_u32(const void* p) {
    uint32_t a;
    asm("{ .reg .u64 t; cvta.to.shared.u64 t, %1; cvt.u32.u64 %0, t; }" : "=r"(a) : "l"(p));
    return a;
}

// MUFU-based exp: exp(x) = ex2(x * log2e). |S| <= ~50 so no range handling.
// MUFU rt=8/SMSP beats the ~14-op FFMA polynomial when all warps hit the
// softmax phase simultaneously (exp phase was ~3.6K fma-pipe cyc/chunk).
__device__ __forceinline__ float fast_exp(float x) {
    float t = x * 1.4426950408889634f;
    float r;
    asm("ex2.approx.f32 %0, %1;" : "=f"(r) : "f"(t));
    return r;
}

// sm_75/80-era ops — legal on EVERY compilation pass.
#define LDSM4(r, a) \
    asm volatile("ldmatrix.sync.aligned.m8n8.x4.shared.b16 {%0,%1,%2,%3},[%4];" \
        : "=r"((r)[0]), "=r"((r)[1]), "=r"((r)[2]), "=r"((r)[3]) : "r"(a))
#define LDSM4T(r, a) \
    asm volatile("ldmatrix.sync.aligned.m8n8.x4.trans.shared.b16 {%0,%1,%2,%3},[%4];" \
        : "=r"((r)[0]), "=r"((r)[1]), "=r"((r)[2]), "=r"((r)[3]) : "r"(a))
#define MOVMAT(d, s) \
    asm volatile("movmatrix.sync.aligned.m8n8.trans.b16 %0, %1;" : "=r"(d) : "r"(s))
#define CP_ASYNC16(dst, src) \
    asm volatile("cp.async.cg.shared.global [%0], [%1], 16;" :: "r"(dst), "l"(src))
#define CP_COMMIT() asm volatile("cp.async.commit_group;" ::: "memory")
#define CP_WAIT0()  asm volatile("cp.async.wait_group 0;" ::: "memory")

__device__ __forceinline__ void mma_bf16(float* d, const uint32_t* a, uint32_t b0, uint32_t b1) {
    asm volatile("mma.sync.aligned.m16n8k16.row.col.f32.bf16.bf16.f32 "
                 "{%0,%1,%2,%3},{%4,%5,%6,%7},{%8,%9},{%0,%1,%2,%3};"
                 : "+f"(d[0]), "+f"(d[1]), "+f"(d[2]), "+f"(d[3])
                 : "r"(a[0]), "r"(a[1]), "r"(a[2]), "r"(a[3]), "r"(b0), "r"(b1));
}

__device__ __forceinline__ uint32_t pack_bf2(float a, float b) {
    __nv_bfloat162 h2 = __floats2bfloat162_rn(a, b);
    uint32_t u; memcpy(&u, &h2, 4); return u;
}

// ---------------------------------------------------------------------------
// Kernel 0: convert Wv fp32 -> split-bf16.
// ---------------------------------------------------------------------------
__global__ void wvconv_kernel(const float* __restrict__ Wv) {
    int idx = blockIdx.x * 256 + threadIdx.x;
    if (idx >= CIN * C8) return;
    float v = Wv[idx];
    __nv_bfloat16 h = __float2bfloat16_rn(v);
    g_wv_h[idx] = h;
    g_wv_l[idx] = __float2bfloat16_rn(v - __bfloat162float(h));
}

// ---------------------------------------------------------------------------
// Kernel 1: QKV — R13 version (proven 52.7us). UNCHANGED.
// ---------------------------------------------------------------------------
#define XP 272
#define WP 144
#define QK_XH 0
#define QK_XL 17408
#define QK_W  34816
#define SMEM_QKV 90112

__global__ __launch_bounds__(256) void qkv_kernel(const float* __restrict__ x,
                                                  const float* __restrict__ Wf,
                                                  const float* __restrict__ Wg,
                                                  const float* __restrict__ Wh) {
    extern __shared__ char sm[];
    const uint32_t sb = smem_u32(sm);
    const int tid = threadIdx.x, wid = tid >> 5, lane = tid & 31;
    const int g = lane >> 2, tg = lane & 3;
    const int n0 = blockIdx.x * 128;
    const int b  = blockIdx.y;
    const float* xb = x + (size_t)b * CIN * NN;
    const float* Wp[3] = { Wf, Wg, Wh };

    const uint32_t at_row = (lane & 7) + ((lane >> 4) & 1) * 8;
    const uint32_t at_cb  = ((lane >> 3) & 1) * 16;
    const uint32_t aX  = sb + QK_XH + at_row * XP + wid * 32 + at_cb;
    const uint32_t aXl = aX + (QK_XL - QK_XH);
    const uint32_t b_row = ((lane >> 4) & 1) * 8 + (lane & 7);
    const uint32_t b_cb  = ((lane >> 3) & 1) * 16;
    const uint32_t aW0 = sb + QK_W + b_row * WP + b_cb;

    float d[3][8][4] = {};

    for (int kci = 0; kci < 8; ++kci) {
        const int kc = kci * 64;
        __syncthreads();
        #pragma unroll
        for (int r = 0; r < 8; ++r) {
            int idx = r * 256 + tid;
            int c = idx >> 5, f4 = idx & 31;
            int n = f4 * 4;
            float4 xv = *(const float4*)&xb[(size_t)(kc + c) * NN + n0 + n];
            __nv_bfloat16 h0 = __float2bfloat16_rn(xv.x);
            __nv_bfloat16 h1 = __float2bfloat16_rn(xv.y);
            __nv_bfloat16 h2 = __float2bfloat16_rn(xv.z);
            __nv_bfloat16 h3 = __float2bfloat16_rn(xv.w);
            uint32_t hA = ((uint32_t)*(uint16_t*)&h1 << 16) | *(uint16_t*)&h0;
            uint32_t hB = ((uint32_t)*(uint16_t*)&h3 << 16) | *(uint16_t*)&h2;
            uint32_t lA = pack_bf2(xv.x - __bfloat162float(h0), xv.y - __bfloat162float(h1));
            uint32_t lB = pack_bf2(xv.z - __bfloat162float(h2), xv.w - __bfloat162float(h3));
            *(uint2*)(sm + QK_XH + c * XP + n * 2) = make_uint2(hA, hB);
            *(uint2*)(sm + QK_XL + c * XP + n * 2) = make_uint2(lA, lB);
        }
        #pragma unroll
        for (int w = 0; w < 3; ++w) {
            const float* W = Wp[w];
            #pragma unroll
            for (int r = 0; r < 4; ++r) {
                int idx = r * 256 + tid;
                int o = idx >> 4, f4 = idx & 15;
                int c = f4 * 4;
                float4 wv = *(const float4*)&W[(size_t)o * CIN + kc + c];
                __nv_bfloat16 h0 = __float2bfloat16_rn(wv.x);
                __nv_bfloat16 h1 = __float2bfloat16_rn(wv.y);
                __nv_bfloat16 h2 = __float2bfloat16_rn(wv.z);
                __nv_bfloat16 h3 = __float2bfloat16_rn(wv.w);
                uint32_t hA = ((uint32_t)*(uint16_t*)&h1 << 16) | *(uint16_t*)&h0;
                uint32_t hB = ((uint32_t)*(uint16_t*)&h3 << 16) | *(uint16_t*)&h2;
                uint32_t lA = pack_bf2(wv.x - __bfloat162float(h0), wv.y - __bfloat162float(h1));
                uint32_t lB = pack_bf2(wv.z - __bfloat162float(h2), wv.w - __bfloat162float(h3));
                *(uint2*)(sm + QK_W + w * 18432 + o * WP + c * 2) = make_uint2(hA, hB);
                *(uint2*)(sm + QK_W + w * 18432 + 9216 + o * WP + c * 2) = make_uint2(lA, lB);
            }
        }
        __syncthreads();

        #pragma unroll
        for (int kt = 0; kt < 4; ++kt) {
            uint32_t ah[4], al[4];
            LDSM4T(ah, aX + kt * 16 * XP);
            LDSM4T(al, aXl + kt * 16 * XP);
            #pragma unroll
            for (int w = 0; w < 3; ++w) {
                const uint32_t aW  = aW0 + w * 18432;
                const uint32_t aWl = aW + 9216;
                #pragma unroll
                for (int p = 0; p < 4; ++p) {
                    uint32_t bh[4], bl[4];
                    LDSM4(bh, aW + p * 16 * WP + kt * 32);
                    LDSM4(bl, aWl + p * 16 * WP + kt * 32);
                    float* d0 = d[w][2 * p];
                    float* d1 = d[w][2 * p + 1];
                    mma_bf16(d0, ah, bh[0], bh[1]);
                    mma_bf16(d1, ah, bh[2], bh[3]);
                    mma_bf16(d0, ah, bl[0], bl[1]);
                    mma_bf16(d1, ah, bl[2], bl[3]);
                    mma_bf16(d0, al, bh[0], bh[1]);
                    mma_bf16(d1, al, bh[2], bh[3]);
                }
            }
        }
    }

    #pragma unroll
    for (int w = 0; w < 3; ++w) {
        if (w < 2) {
            __nv_bfloat16* dh = (w == 0) ? g_ft_h : g_gt_h;
            __nv_bfloat16* dl = (w == 0) ? g_ft_l : g_gt_l;
            #pragma unroll
            for (int ot = 0; ot < 8; ++ot) {
                int o = ot * 8 + 2 * tg;
                int n_a = n0 + wid * 16 + g;
                size_t base_a = ((size_t)b * NN + n_a) * C8 + o;
                size_t base_b = base_a + 8 * C8;
                float v0 = d[w][ot][0], v1 = d[w][ot][1], v2 = d[w][ot][2], v3 = d[w][ot][3];
                __nv_bfloat16 h0 = __float2bfloat16_rn(v0);
                __nv_bfloat16 h1 = __float2bfloat16_rn(v1);
                __nv_bfloat16 h2 = __float2bfloat16_rn(v2);
                __nv_bfloat16 h3 = __float2bfloat16_rn(v3);
                *(uint32_t*)&dh[base_a] = ((uint32_t)*(uint16_t*)&h1 << 16) | *(uint16_t*)&h0;
                *(uint32_t*)&dh[base_b] = ((uint32_t)*(uint16_t*)&h3 << 16) | *(uint16_t*)&h2;
                *(uint32_t*)&dl[base_a] = pack_bf2(v0 - __bfloat162float(h0), v1 - __bfloat162float(h1));
                *(uint32_t*)&dl[base_b] = pack_bf2(v2 - __bfloat162float(h2), v3 - __bfloat162float(h3));
            }
        } else {
            #pragma unroll
            for (int ot = 0; ot < 8; ++ot) {
                int o = ot * 8 + 2 * tg;
                int n_a = n0 + wid * 16 + g;
                #pragma unroll
                for (int e = 0; e < 2; ++e) {
                    #pragma unroll
                    for (int rr = 0; rr < 2; ++rr) {
                        float v = d[w][ot][rr * 2 + e];
                        size_t idx = ((size_t)b * C8 + o + e) * NN + n_a + rr * 8;
                        __nv_bfloat16 h = __float2bfloat16_rn(v);
                        g_h_h[idx] = h;
                        g_h_l[idx] = __float2bfloat16_rn(v - __bfloat162float(h));
                    }
                }
            }
        }
    }
}

// ---------------------------------------------------------------------------
// Kernel 2: flash attention — R13 loop with MUFU exp; split-bf16 ao epilogue.
// ---------------------------------------------------------------------------
#define AQ_PITCH 144
#define AT_QH 0
#define AT_QL 18432
#define AT_KV 36864
#define AT_OSM 0
#define AT_RED 131072
#define AT_LINV 133120
#define SMEM_ATTN 184320

__global__ __launch_bounds__(512, 1) void attn_kernel() {
    extern __shared__ char sm[];
    const uint32_t sb = smem_u32(sm);
    const int tid = threadIdx.x, wid = tid >> 5, lane = tid & 31;
    const int g = lane >> 2, tg = lane & 3;
    const int wi = wid & 3, wj = wid >> 2;
    const int j0 = blockIdx.x * 128;
    const int b  = blockIdx.y;

    const uint4* kh_g = (const uint4*)(g_ft_h + (size_t)b * NN * C8);
    const uint4* kl_g = (const uint4*)(g_ft_l + (size_t)b * NN * C8);
    const uint4* vh_g = (const uint4*)(g_h_h + (size_t)b * C8 * NN);
    const uint4* vl_g = (const uint4*)(g_h_l + (size_t)b * C8 * NN);

    {
        const uint4* qh = (const uint4*)(g_gt_h + ((size_t)b * NN + j0) * C8);
        const uint4* ql = (const uint4*)(g_gt_l + ((size_t)b * NN + j0) * C8);
        #pragma unroll
        for (int r = 0; r < 2; ++r) {
            int u = r * 512 + tid;
            int row = u >> 3, q = u & 7;
            *(uint4*)(sm + AT_QH + row * AQ_PITCH + q * 16) = qh[row * 8 + q];
            *(uint4*)(sm + AT_QL + row * AQ_PITCH + q * 16) = ql[row * 8 + q];
        }
    }

    const uint32_t offK = (wi * 16 + (lane & 15)) * AQ_PITCH + ((lane >> 4) & 1) * 16;
    const uint32_t offV0 = 18432 + (lane & 15) * AQ_PITCH + wi * 32 + ((lane >> 4) & 1) * 16;
    const uint32_t b_row = ((lane >> 4) & 1) * 8 + (lane & 7);
    const uint32_t b_cb  = ((lane >> 3) & 1) * 16;
    uint32_t aQ[2], aQl[2];
    #pragma unroll
    for (int ntp = 0; ntp < 2; ++ntp) {
        aQ[ntp]  = sb + AT_QH + (wj * 32 + ntp * 16 + b_row) * AQ_PITCH + b_cb;
        aQl[ntp] = aQ[ntp] + (AT_QL - AT_QH);
    }

    auto stage_chunk = [&](int it2, int cbuf) {
        const uint32_t cb = sb + AT_KV + cbuf * 73728;
        int row = tid >> 3, q = tid & 7;
        #pragma unroll
        for (int sub = 0; sub < 2; ++sub) {
            const int i0 = it2 * 128 + sub * 64;
            uint32_t drow = cb + sub * 36864 + row * AQ_PITCH + q * 16;
            CP_ASYNC16(drow, kh_g + (size_t)(i0 + row) * 8 + q);
            CP_ASYNC16(drow + 9216, kl_g + (size_t)(i0 + row) * 8 + q);
            size_t vsrc = (size_t)row * (NN / 8) + (i0 >> 3) + q;
            CP_ASYNC16(drow + 18432, vh_g + vsrc);
            CP_ASYNC16(drow + 27648, vl_g + vsrc);
        }
    };

    stage_chunk(0, 0);
    CP_COMMIT();

    float o[16][4] = {};
    float ls[8] = {};

    for (int it2 = 0; it2 < 32; ++it2) {
        const int cbuf = it2 & 1;
        const uint32_t cb = sb + AT_KV + cbuf * 73728;
        CP_WAIT0();
        __syncthreads();

        float d[2][4][4] = {};
        #pragma unroll
        for (int kt = 0; kt < 4; ++kt) {
            uint32_t qh0[4], ql0[4], qh1[4], ql1[4];
            LDSM4(qh0, aQ[0] + kt * 32);
            LDSM4(ql0, aQl[0] + kt * 32);
            LDSM4(qh1, aQ[1] + kt * 32);
            LDSM4(ql1, aQl[1] + kt * 32);
            #pragma unroll
            for (int sub = 0; sub < 2; ++sub) {
                const uint32_t aK = cb + sub * 36864 + offK;
                uint32_t ah[4], al[4];
                LDSM4(ah, aK + kt * 32);
                LDSM4(al, aK + 9216 + kt * 32);
                float* d0 = d[sub][0];
                float* d1 = d[sub][1];
                float* d2 = d[sub][2];
                float* d3 = d[sub][3];
                mma_bf16(d0, ah, qh0[0], qh0[1]);
                mma_bf16(d1, ah, qh0[2], qh0[3]);
                mma_bf16(d2, ah, qh1[0], qh1[1]);
                mma_bf16(d3, ah, qh1[2], qh1[3]);
                mma_bf16(d0, ah, ql0[0], ql0[1]);
                mma_bf16(d1, ah, ql0[2], ql0[3]);
                mma_bf16(d2, ah, ql1[0], ql1[1]);
                mma_bf16(d3, ah, ql1[2], ql1[3]);
                mma_bf16(d0, al, qh0[0], qh0[1]);
                mma_bf16(d1, al, qh0[2], qh0[3]);
                mma_bf16(d2, al, qh1[0], qh1[1]);
                mma_bf16(d3, al, qh1[2], qh1[3]);
            }
        }

        if (it2 + 1 < 32) {
            stage_chunk(it2 + 1, cbuf ^ 1);
            CP_COMMIT();
        }

        #pragma unroll
        for (int sub = 0; sub < 2; ++sub) {
            uint32_t pb[4][4];
            #pragma unroll
            for (int nt = 0; nt < 4; ++nt) {
                float e0 = fast_exp(d[sub][nt][0]);
                float e1 = fast_exp(d[sub][nt][1]);
                float e2 = fast_exp(d[sub][nt][2]);
                float e3 = fast_exp(d[sub][nt][3]);
                ls[nt * 2]     += e0 + e2;
                ls[nt * 2 + 1] += e1 + e3;
                __nv_bfloat162 hA = __floats2bfloat162_rn(e0, e1);
                __nv_bfloat162 hB = __floats2bfloat162_rn(e2, e3);
                uint32_t uhA, uhB; memcpy(&uhA, &hA, 4); memcpy(&uhB, &hB, 4);
                uint32_t ulA = pack_bf2(e0 - __bfloat162float(hA.x), e1 - __bfloat162float(hA.y));
                uint32_t ulB = pack_bf2(e2 - __bfloat162float(hB.x), e3 - __bfloat162float(hB.y));
                MOVMAT(pb[nt][0], uhA);
                MOVMAT(pb[nt][1], uhB);
                MOVMAT(pb[nt][2], ulA);
                MOVMAT(pb[nt][3], ulB);
            }
            #pragma unroll
            for (int ct = 0; ct < 4; ++ct) {
                uint32_t vh[4], vl[4];
                uint32_t aV = cb + sub * 36864 + offV0 + ct * (16 * AQ_PITCH);
                LDSM4(vh, aV);
                LDSM4(vl, aV + 9216);
                #pragma unroll
                for (int nt = 0; nt < 4; ++nt) {
                    float* oo = o[ct * 4 + nt];
                    mma_bf16(oo, vh, pb[nt][0], pb[nt][1]);
                    mma_bf16(oo, vh, pb[nt][2], pb[nt][3]);
                    mma_bf16(oo, vl, pb[nt][0], pb[nt][1]);
                }
            }
        }
    }

    __syncthreads();

    float* Osm = (float*)(sm + AT_OSM);
    #pragma unroll
    for (int ct = 0; ct < 4; ++ct) {
        #pragma unroll
        for (int nt = 0; nt < 4; ++nt) {
            int c = ct * 16 + g;
            int jc = wj * 32 + nt * 8 + 2 * tg;
            float* os = Osm + ((size_t)wi * 64 + c) * 128 + jc;
            os[0] = o[ct * 4 + nt][0];
            os[1] = o[ct * 4 + nt][1];
            os[8 * 128] = o[ct * 4 + nt][2];
            os[8 * 128 + 1] = o[ct * 4 + nt][3];
        }
    }
    float* red = (float*)(sm + AT_RED);
    #pragma unroll
    for (int nt = 0; nt < 4; ++nt) {
        #pragma unroll
        for (int e = 0; e < 2; ++e) {
            float v = ls[nt * 2 + e];
            v += __shfl_down_sync(0xffffffffu, v, 4);
            v += __shfl_down_sync(0xffffffffu, v, 8);
            v += __shfl_down_sync(0xffffffffu, v, 16);
            if (lane < 4)
                red[wi * 128 + wj * 32 + nt * 8 + 2 * lane + e] = v;
        }
    }
    __syncthreads();

    float* linv = (float*)(sm + AT_LINV);
    if (tid < 128)
        linv[tid] = 1.0f / (red[tid] + red[128 + tid] + red[256 + tid] + red[384 + tid]);
    __syncthreads();

    {
        const int j = tid & 127;
        const int cg = tid >> 7;
        float inv = linv[j];
        size_t base = (size_t)b * C8 * NN + j0 + j;
        #pragma unroll
        for (int k = 0; k < 16; ++k) {
            int c = cg * 16 + k;
            float v = (Osm[(size_t)c * 128 + j]
                     + Osm[(size_t)(64 + c) * 128 + j]
                     + Osm[(size_t)(128 + c) * 128 + j]
                     + Osm[(size_t)(192 + c) * 128 + j]) * inv;
            __nv_bfloat16 h = __float2bfloat16_rn(v);
            g_ao_h[base + (size_t)c * NN] = h;
            g_ao_l[base + (size_t)c * NN] = __float2bfloat16_rn(v - __bfloat162float(h));
        }
    }
}

// ---------------------------------------------------------------------------
// Kernel 3: proj on mma.sync, m-SPLIT: grid (32 j, 4 b, 2 m-halves).
// smem ~106 KB -> 2 blocks/SM; staging/store latency overlaps across blocks.
// ---------------------------------------------------------------------------
#define PR_WV 0                 // hi: 256*144 = 36864, lo +36864
#define PR_AOH 73728            // 64 x 272
#define PR_AOL 91136
#define SMEM_PROJ 108544

__global__ __launch_bounds__(512) void proj_kernel(const float* __restrict__ x,
                                                   const float* __restrict__ gammap,
                                                   float* __restrict__ out) {
    extern __shared__ char sm[];
    const uint32_t sb = smem_u32(sm);
    const int tid = threadIdx.x, wid = tid >> 5, lane = tid & 31;
    const int g = lane >> 2, tg = lane & 3;
    const int j0 = blockIdx.x * 128;
    const int b  = blockIdx.y;
    const int mh = blockIdx.z;          // m half: rows [mh*256, mh*256+256)

    // stage Wv half (256 x 64, hi/lo) and ao tile (64 x 128, hi/lo)
    #pragma unroll
    for (int r = 0; r < 4; ++r) {
        int idx = r * 512 + tid;
        int row = idx >> 3, seg = idx & 7;
        uint32_t dst = sb + PR_WV + row * 144 + seg * 16;
        size_t srcI = (size_t)(mh * 256 + row) * C8 + seg * 8;
        CP_ASYNC16(dst, (const char*)g_wv_h + srcI * 2);
        CP_ASYNC16(dst + 36864, (const char*)g_wv_l + srcI * 2);
    }
    #pragma unroll
    for (int r = 0; r < 2; ++r) {
        int idx = r * 512 + tid;
        int c = idx >> 4, seg = idx & 15;
        uint32_t dst = sb + PR_AOH + c * 272 + seg * 16;
        size_t srcI = ((size_t)b * C8 + c) * NN + j0 + seg * 8;
        CP_ASYNC16(dst, (const char*)g_ao_h + srcI * 2);
        CP_ASYNC16(dst + (PR_AOL - PR_AOH), (const char*)g_ao_l + srcI * 2);
    }
    CP_COMMIT();
    CP_WAIT0();
    __syncthreads();

    const float gamma = gammap[0];
    float* outSA = out + (size_t)NB * CIN * NN;
    const uint32_t aoB = sb + PR_AOH +
        (((lane >> 3) & 1) * 8 + (lane & 7)) * 272 + ((lane >> 4) & 1) * 16;
    const int m0 = mh * 256 + wid * 16;
    const uint32_t aWv = sb + PR_WV +
        (wid * 16 + (lane & 15)) * 144 + ((lane >> 4) & 1) * 16;

    float dd[16][4] = {};
    #pragma unroll
    for (int kt = 0; kt < 4; ++kt) {
        uint32_t ah[4], al[4];
        LDSM4(ah, aWv + kt * 32);
        LDSM4(al, aWv + 36864 + kt * 32);
        #pragma unroll
        for (int jb = 0; jb < 8; ++jb) {
            uint32_t bh[4], bl[4];
            LDSM4T(bh, aoB + kt * (16 * 272) + jb * 32);
            LDSM4T(bl, aoB + (PR_AOL - PR_AOH) + kt * (16 * 272) + jb * 32);
            float* d0 = dd[jb * 2];
            float* d1 = dd[jb * 2 + 1];
            mma_bf16(d0, ah, bh[0], bh[1]);
            mma_bf16(d1, ah, bh[2], bh[3]);
            mma_bf16(d0, ah, bl[0], bl[1]);
            mma_bf16(d1, ah, bl[2], bl[3]);
            mma_bf16(d0, al, bh[0], bh[1]);
            mma_bf16(d1, al, bh[2], bh[3]);
        }
    }
    #pragma unroll
    for (int jt = 0; jt < 16; ++jt) {
        int jc = j0 + jt * 8 + 2 * tg;
        #pragma unroll
        for (int rr = 0; rr < 2; ++rr) {
            int m = m0 + g + rr * 8;
            size_t base = ((size_t)b * CIN + m) * NN + jc;
            float s0 = dd[jt][rr * 2], s1 = dd[jt][rr * 2 + 1];
            float2 xv = *(const float2*)&x[base];
            *(float2*)&outSA[base] = make_float2(s0, s1);
            *(float2*)&out[base] =
                make_float2(fmaf(s0, gamma, xv.x), fmaf(s1, gamma, xv.y));
        }
    }
}

extern "C" void kernel_launch(void* const* d_in, const int* in_sizes, int n_in,
                              void* d_out, int out_size) {
    const float* x     = (const float*)d_in[0];
    const float* Wf    = (const float*)d_in[1];
    const float* Wg    = (const float*)d_in[2];
    const float* Wh    = (const float*)d_in[3];
    const float* Wv    = (const float*)d_in[4];
    const float* gamma = (const float*)d_in[5];
    float* out = (float*)d_out;

    cudaFuncSetAttribute(qkv_kernel,
                         cudaFuncAttributeMaxDynamicSharedMemorySize, SMEM_QKV);
    cudaFuncSetAttribute(attn_kernel,
                         cudaFuncAttributeMaxDynamicSharedMemorySize, SMEM_ATTN);
    cudaFuncSetAttribute(proj_kernel,
                         cudaFuncAttributeMaxDynamicSharedMemorySize, SMEM_PROJ);

    wvconv_kernel<<<128, 256>>>(Wv);
    qkv_kernel<<<dim3(32, 4), 256, SMEM_QKV>>>(x, Wf, Wg, Wh);
    attn_kernel<<<dim3(32, 4), 512, SMEM_ATTN>>>();
    proj_kernel<<<dim3(32, 4, 2), 512, SMEM_PROJ>>>(x, gamma, out);
}